// round 16
// baseline (speedup 1.0000x reference)
#include <cuda_runtime.h>
#include <cuda_bf16.h>
#include <cstdint>

#define B_    8
#define S_    4096
#define Hd    512
#define KD    512
#define NC    1024
#define Mrows 32768
#define CH    32
#define CL    128
#define NOUT  16777216

// ---------------- scratch (device globals; no allocations allowed) ----------
__device__ __nv_bfloat16 g_Ah0[(size_t)Mrows * KD];   // x hi (layer0 A)
__device__ __nv_bfloat16 g_Al0[(size_t)Mrows * KD];   // x lo
__device__ __nv_bfloat16 g_Ah1[(size_t)Mrows * KD];   // h0 hi (layer1 A)
__device__ __nv_bfloat16 g_Al1[(size_t)Mrows * KD];   // h0 lo
__device__ __nv_bfloat16 g_Wh[2][(size_t)NC * KD];    // W hi, gate/hidden row-interleaved
__device__ __nv_bfloat16 g_Wl[2][(size_t)NC * KD];    // W lo
__device__ float         g_bI[2][NC];                 // bias, interleaved
__device__ float2        g_AV[(size_t)Mrows * Hd];    // (a, v) pairs
__device__ float2        g_carry[B_ * CH * Hd];
__device__ float         g_hstart[B_ * CH * Hd];

// ---------------- PTX helpers (baseline sm_80-class only) -------------------
__device__ __forceinline__ uint32_t s2u(const void* p) {
    uint32_t a;
    asm("{ .reg .u64 t; cvta.to.shared.u64 t, %1; cvt.u32.u64 %0, t; }" : "=r"(a) : "l"(p));
    return a;
}
__device__ __forceinline__ void cp16(uint32_t s, const void* g) {
    asm volatile("cp.async.cg.shared.global [%0], [%1], 16;" :: "r"(s), "l"(g) : "memory");
}
__device__ __forceinline__ void cp_commit() {
    asm volatile("cp.async.commit_group;" ::: "memory");
}
template <int N> __device__ __forceinline__ void cp_wait() {
    asm volatile("cp.async.wait_group %0;" :: "n"(N) : "memory");
}
__device__ __forceinline__ void ldsm4(uint32_t* d, uint32_t a) {
    asm volatile("ldmatrix.sync.aligned.m8n8.x4.shared.b16 {%0,%1,%2,%3}, [%4];"
                 : "=r"(d[0]), "=r"(d[1]), "=r"(d[2]), "=r"(d[3]) : "r"(a));
}
__device__ __forceinline__ void mma16816(float* c, const uint32_t* a, uint32_t b0, uint32_t b1) {
    asm volatile(
        "mma.sync.aligned.m16n8k16.row.col.f32.bf16.bf16.f32 "
        "{%0,%1,%2,%3}, {%4,%5,%6,%7}, {%8,%9}, {%0,%1,%2,%3};"
        : "+f"(c[0]), "+f"(c[1]), "+f"(c[2]), "+f"(c[3])
        : "r"(a[0]), "r"(a[1]), "r"(a[2]), "r"(a[3]), "r"(b0), "r"(b1));
}
__device__ __forceinline__ uint32_t pkbf(__nv_bfloat16 a, __nv_bfloat16 b) {
    __nv_bfloat162 t; t.x = a; t.y = b;
    return *reinterpret_cast<uint32_t*>(&t);
}

// ---------------- converters ------------------------------------------------
__global__ void convert_x(const float4* __restrict__ x4) {
    size_t i = (size_t)blockIdx.x * blockDim.x + threadIdx.x;   // 4M threads
    float4 v = x4[i];
    __nv_bfloat16 h0 = __float2bfloat16(v.x), h1 = __float2bfloat16(v.y);
    __nv_bfloat16 h2 = __float2bfloat16(v.z), h3 = __float2bfloat16(v.w);
    __nv_bfloat16 l0 = __float2bfloat16(v.x - __bfloat162float(h0));
    __nv_bfloat16 l1 = __float2bfloat16(v.y - __bfloat162float(h1));
    __nv_bfloat16 l2 = __float2bfloat16(v.z - __bfloat162float(h2));
    __nv_bfloat16 l3 = __float2bfloat16(v.w - __bfloat162float(h3));
    reinterpret_cast<uint2*>(g_Ah0)[i] = make_uint2(pkbf(h0, h1), pkbf(h2, h3));
    reinterpret_cast<uint2*>(g_Al0)[i] = make_uint2(pkbf(l0, l1), pkbf(l2, l3));
}

__global__ void convert_w(const float* __restrict__ w0, const float* __restrict__ w1,
                          const float* __restrict__ b0, const float* __restrict__ b1) {
    int idx = blockIdx.x * blockDim.x + threadIdx.x;   // 0 .. 2*1024*128-1
    int l   = idx >> 17;
    int rem = idx & 131071;
    int r   = rem >> 7;      // interleaved dst row 0..1023
    int k4  = rem & 127;
    const float* w = l ? w1 : w0;
    int sr = (r & 1) ? (Hd + (r >> 1)) : (r >> 1);
    float4 v = *reinterpret_cast<const float4*>(w + (size_t)sr * KD + k4 * 4);
    __nv_bfloat16 h0 = __float2bfloat16(v.x), h1 = __float2bfloat16(v.y);
    __nv_bfloat16 h2 = __float2bfloat16(v.z), h3 = __float2bfloat16(v.w);
    __nv_bfloat16 l0 = __float2bfloat16(v.x - __bfloat162float(h0));
    __nv_bfloat16 l1 = __float2bfloat16(v.y - __bfloat162float(h1));
    __nv_bfloat16 l2 = __float2bfloat16(v.z - __bfloat162float(h2));
    __nv_bfloat16 l3 = __float2bfloat16(v.w - __bfloat162float(h3));
    size_t o = (size_t)r * KD + k4 * 4;
    reinterpret_cast<uint2*>(g_Wh[l] + o)[0] = make_uint2(pkbf(h0, h1), pkbf(h2, h3));
    reinterpret_cast<uint2*>(g_Wl[l] + o)[0] = make_uint2(pkbf(l0, l1), pkbf(l2, l3));
    if (k4 == 0) g_bI[l][r] = (l ? b1 : b0)[sr];
}

// ---------------- HMMA GEMM + fused gate epilogue + fused chunk-scan --------
// C[M=32768, N=1024] over effective K' = 3*512 (bf16 3-split):
//   seg0: Ah*Wh   seg1: Al*Wh   seg2: Ah*Wl
// Tile 128x128, BK=64, 256 threads, 8 warps (2 m x 4 n), warp tile 64x32.
// 144B smem rows -> conflict-free ldmatrix. 3-stage cp.async pipeline.
// CTA M-tile == one scan chunk (CL=128): epilogue stages (a,v) in smem,
// computes the chunk aggregate (P,Q) in-kernel, and writes g_AV coalesced.
#define NSTG   3
#define KTILES 24                       // 3 segments * 8 k-chunks of 64
#define ROWB   144                      // 64 bf16 (128B) + 16B pad
#define OPBYT  (128 * ROWB)             // 18432 per operand
#define STGBYT (2 * OPBYT)              // 36864 per stage
#define SMEM_DYN (NSTG * STGBYT)        // 110592
#define AVSTR  66                       // float2 stride of epilogue staging row

__global__ void __launch_bounds__(256, 2) gemm_kernel(int layer)
{
    extern __shared__ __align__(1024) char dsm[];
    const uint32_t base = s2u(dsm);

    const int tid  = threadIdx.x;
    const int lane = tid & 31;
    const int wid  = tid >> 5;
    const int wm   = wid & 1;           // 0..1 -> 64 rows each
    const int wn   = wid >> 1;          // 0..3 -> 32 cols each
    const int bn   = blockIdx.x;        // 0..7
    const int bm   = blockIdx.y;        // 0..255  == b*CH + c

    const __nv_bfloat16* __restrict__ Ah = layer ? g_Ah1 : g_Ah0;
    const __nv_bfloat16* __restrict__ Al = layer ? g_Al1 : g_Al0;
    const __nv_bfloat16* __restrict__ Wh = g_Wh[layer];
    const __nv_bfloat16* __restrict__ Wl = g_Wl[layer];

    // ---- async loader: thread covers 64B (4x16B) of one 128B row, A and B --
    const int lrow = tid >> 1;          // 0..127
    const int lq   = tid & 1;           // which 64B half of the 128B row
    const size_t ga_row = (size_t)(bm * 128 + lrow) * KD;
    const size_t gb_row = (size_t)(bn * 128 + lrow) * KD;
    const uint32_t sa_off = (uint32_t)(lrow * ROWB + lq * 64);

    auto load_stage = [&](int kt, int slot) {
        const int seg = kt >> 3, kc = kt & 7;
        const __nv_bfloat16* __restrict__ Ap = (seg == 1) ? Al : Ah;
        const __nv_bfloat16* __restrict__ Bp = (seg == 2) ? Wl : Wh;
        const __nv_bfloat16* ga = Ap + ga_row + kc * 64 + lq * 32;
        const __nv_bfloat16* gb = Bp + gb_row + kc * 64 + lq * 32;
        uint32_t sa = base + slot * STGBYT + sa_off;
        uint32_t sb = sa + OPBYT;
#pragma unroll
        for (int j = 0; j < 4; ++j) {
            cp16(sa + j * 16, ga + j * 8);
            cp16(sb + j * 16, gb + j * 8);
        }
    };

    // ---- per-lane ldmatrix bases -------------------------------------------
    const int lr8 = (lane & 7) + ((lane >> 3) & 1) * 8;   // row within 16-row frag
    const int lc  = (lane >> 4) & 1;                      // 16B half select
    const uint32_t a_lb = (uint32_t)((wm * 64 + lr8) * ROWB + lc * 16);
    const uint32_t b_lb = (uint32_t)((wn * 32 + lr8) * ROWB + lc * 16) + OPBYT;

    float acc[4][4][4];
#pragma unroll
    for (int i = 0; i < 4; ++i)
#pragma unroll
        for (int j = 0; j < 4; ++j)
#pragma unroll
            for (int q = 0; q < 4; ++q) acc[i][j][q] = 0.0f;

    // ---- pipeline prologue: stages 0..NSTG-2 -------------------------------
#pragma unroll
    for (int p = 0; p < NSTG - 1; ++p) { load_stage(p, p); cp_commit(); }

    uint32_t afr[2][4][4], bfr[2][2][4];

#pragma unroll 1
    for (int kt = 0; kt < KTILES; ++kt) {
        cp_wait<NSTG - 2>();
        __syncthreads();
        if (kt + NSTG - 1 < KTILES) load_stage(kt + NSTG - 1, (kt + NSTG - 1) % NSTG);
        cp_commit();

        const uint32_t stg   = base + (kt % NSTG) * STGBYT;
        const uint32_t abase = stg + a_lb;
        const uint32_t bbase = stg + b_lb;

        // kf=0 fragments
#pragma unroll
        for (int mf = 0; mf < 4; ++mf) ldsm4(afr[0][mf], abase + mf * (16 * ROWB));
#pragma unroll
        for (int n2 = 0; n2 < 2; ++n2) ldsm4(bfr[0][n2], bbase + n2 * (16 * ROWB));

#pragma unroll
        for (int kf = 0; kf < 4; ++kf) {
            const int cur = kf & 1, nxt = cur ^ 1;
            if (kf < 3) {
#pragma unroll
                for (int mf = 0; mf < 4; ++mf)
                    ldsm4(afr[nxt][mf], abase + mf * (16 * ROWB) + (kf + 1) * 32);
#pragma unroll
                for (int n2 = 0; n2 < 2; ++n2)
                    ldsm4(bfr[nxt][n2], bbase + n2 * (16 * ROWB) + (kf + 1) * 32);
            }
#pragma unroll
            for (int mf = 0; mf < 4; ++mf)
#pragma unroll
                for (int nf = 0; nf < 4; ++nf) {
                    const int n2 = nf >> 1, w = nf & 1;
                    mma16816(acc[mf][nf], afr[cur][mf], bfr[cur][n2][w], bfr[cur][n2][w + 2]);
                }
        }
    }

    // ---- drain pipeline, reuse stage smem as (a,v) staging -----------------
    cp_wait<0>();
    __syncthreads();
    float2* __restrict__ sav = reinterpret_cast<float2*>(dsm);   // [s][h] s-stride AVSTR

    const float* __restrict__ bi = g_bI[layer];
    const int nq = lane & 3;                          // quad col
    const int nbase = bn * 128 + wn * 32 + nq * 2;    // interleaved gate col
    float bg[4], bh[4];
#pragma unroll
    for (int nf = 0; nf < 4; ++nf) {
        bg[nf] = bi[nbase + nf * 8];
        bh[nf] = bi[nbase + nf * 8 + 1];
    }
    const int srow = wm * 64 + (lane >> 2);           // local s of frag row 0
    const int hloc = wn * 16 + nq;                    // local h of frag col 0

#pragma unroll
    for (int mf = 0; mf < 4; ++mf)
#pragma unroll
        for (int nf = 0; nf < 4; ++nf)
#pragma unroll
            for (int half = 0; half < 2; ++half) {
                float ga = acc[mf][nf][2 * half]     + bg[nf];
                float hd = acc[mf][nf][2 * half + 1] + bh[nf];
                float a  = __fdividef(1.0f, 1.0f + __expf(ga));
                float z  = __fdividef(1.0f, 1.0f + __expf(-ga));
                float g  = (hd >= 0.0f) ? (hd + 0.5f)
                                        : __fdividef(1.0f, 1.0f + __expf(-hd));
                int s = srow + mf * 16 + half * 8;
                sav[s * AVSTR + hloc + nf * 4] = make_float2(a, z * g);
            }
    __syncthreads();

    // ---- fused scanA: chunk aggregate (P, Q) for 64 h's --------------------
    if (tid < 64) {
        float P = 1.0f, Q = 0.0f;
#pragma unroll 4
        for (int s = 0; s < CL; ++s) {
            float2 av = sav[s * AVSTR + tid];
            Q = fmaf(av.x, Q, av.y);
            P *= av.x;
        }
        g_carry[bm * Hd + bn * 64 + tid] = make_float2(P, Q);
    }

    // ---- coalesced g_AV store: 4096 uint4 by 256 threads -------------------
    {
        const uint4* __restrict__ src = reinterpret_cast<const uint4*>(dsm);
        uint4* __restrict__ dstb = reinterpret_cast<uint4*>(g_AV + (size_t)(bm * 128) * Hd + bn * 64);
#pragma unroll
        for (int j = 0; j < 16; ++j) {
            int v = tid + j * 256;          // 0..4095
            int s = v >> 5, u = v & 31;     // 32 uint4 per s-row
            dstb[(size_t)s * (Hd / 2) + u] = src[s * (AVSTR / 2) + u];
        }
    }
}

// ---------------- scanB: serial over CH chunk aggregates --------------------
__global__ void scanB_kernel()
{
    int h = threadIdx.x;
    int b = blockIdx.x;
    float2 pq[CH];
#pragma unroll
    for (int c = 0; c < CH; ++c) pq[c] = g_carry[(b * CH + c) * Hd + h];
    float hc = 0.5f;
#pragma unroll
    for (int c = 0; c < CH; ++c) {
        g_hstart[(b * CH + c) * Hd + h] = hc;
        hc = fmaf(pq[c].x, hc, pq[c].y);
    }
}

// ---------------- scanC: replay chunks, write outputs -----------------------
__global__ void scanC_kernel(int layer, float* __restrict__ Oout)
{
    int h = threadIdx.x;
    int c = blockIdx.x & (CH - 1);
    int b = blockIdx.x >> 5;
    float hc = g_hstart[(b * CH + c) * Hd + h];
    size_t base = ((size_t)b * S_ + (size_t)c * CL) * Hd + h;
    const float2* p = g_AV + base;
    if (layer) {
        float* o = Oout + base;
#pragma unroll 4
        for (int s = 0; s < CL; ++s) {
            float2 av = p[(size_t)s * Hd];
            hc = fmaf(av.x, hc, av.y);
            o[(size_t)s * Hd] = hc;
        }
    } else {
        __nv_bfloat16* oh = g_Ah1 + base;
        __nv_bfloat16* ol = g_Al1 + base;
#pragma unroll 4
        for (int s = 0; s < CL; ++s) {
            float2 av = p[(size_t)s * Hd];
            hc = fmaf(av.x, hc, av.y);
            __nv_bfloat16 hi = __float2bfloat16(hc);
            oh[(size_t)s * Hd] = hi;
            ol[(size_t)s * Hd] = __float2bfloat16(hc - __bfloat162float(hi));
        }
    }
}

// ---------------- tail: stacked next_hidden (2, B, 1, H) --------------------
__global__ void tail_kernel(float* __restrict__ out)
{
    int t = blockIdx.x * blockDim.x + threadIdx.x;   // 0..4095 = b*Hd + h
    int b = t >> 9, h = t & (Hd - 1);
    size_t row = ((size_t)b * S_ + (S_ - 1)) * Hd + h;
    out[NOUT + t] = __bfloat162float(g_Ah1[row]) + __bfloat162float(g_Al1[row]);
    out[NOUT + B_ * Hd + t] = out[row];
}

// ---------------- launch ----------------------------------------------------
extern "C" void kernel_launch(void* const* d_in, const int* in_sizes, int n_in,
                              void* d_out, int out_size)
{
    const float* x  = (const float*)d_in[0];
    const float* w0 = (const float*)d_in[1];
    const float* b0 = (const float*)d_in[2];
    const float* w1 = (const float*)d_in[3];
    const float* b1 = (const float*)d_in[4];
    float* out = (float*)d_out;

    cudaFuncSetAttribute(gemm_kernel, cudaFuncAttributeMaxDynamicSharedMemorySize, SMEM_DYN);

    convert_x<<<16384, 256>>>((const float4*)x);
    convert_w<<<1024, 256>>>(w0, w1, b0, b1);

    dim3 gg(8, 256);   // bn fast: 8 CTAs share each A tile in L2

    // layer 0
    gemm_kernel<<<gg, 256, SMEM_DYN>>>(0);
    scanB_kernel<<<B_, Hd>>>();
    scanC_kernel<<<B_ * CH, Hd>>>(0, out);

    // layer 1
    gemm_kernel<<<gg, 256, SMEM_DYN>>>(1);
    scanB_kernel<<<B_, Hd>>>();
    scanC_kernel<<<B_ * CH, Hd>>>(1, out);

    tail_kernel<<<8, 512>>>(out);
}